// round 7
// baseline (speedup 1.0000x reference)
#include <cuda_runtime.h>
#include <cuda_bf16.h>
#include <cstdint>

#define Bb 4
#define Tt 2048
#define Cc 1024
#define NHh 16
#define Dd 64
#define Mtot (Bb * Tt)   // 8192

// ------------------------- scratch (__device__ globals) --------------------
__device__ float g_qkv[(size_t)Bb * Tt * 3 * Cc];    // [B,T,3C] fp32
__device__ __nv_bfloat16 g_xh[(size_t)Mtot * Cc];
__device__ __nv_bfloat16 g_xl[(size_t)Mtot * Cc];
__device__ __nv_bfloat16 g_wh[(size_t)3 * Cc * Cc];
__device__ __nv_bfloat16 g_wl[(size_t)3 * Cc * Cc];
__device__ __nv_bfloat16 g_ph[(size_t)Cc * Cc];
__device__ __nv_bfloat16 g_pl[(size_t)Cc * Cc];
__device__ __nv_bfloat16 g_ah[(size_t)Mtot * Cc];
__device__ __nv_bfloat16 g_al[(size_t)Mtot * Cc];
// head-major [b*16+h][t][d] bf16 for attention
__device__ __nv_bfloat16 g_qh[(size_t)Mtot * Cc];
__device__ __nv_bfloat16 g_ql[(size_t)Mtot * Cc];
__device__ __nv_bfloat16 g_kh[(size_t)Mtot * Cc];
__device__ __nv_bfloat16 g_kl[(size_t)Mtot * Cc];
__device__ __nv_bfloat16 g_vh[(size_t)Mtot * Cc];
__device__ __nv_bfloat16 g_vl[(size_t)Mtot * Cc];

// ------------------------- helpers -----------------------------------------
__device__ __forceinline__ uint32_t smem_u32(const void* p) {
    uint32_t a;
    asm("{ .reg .u64 t; cvta.to.shared.u64 t, %1; cvt.u32.u64 %0, t; }"
        : "=r"(a) : "l"(p));
    return a;
}

__device__ __forceinline__ void ldmx4(uint32_t& r0, uint32_t& r1,
                                      uint32_t& r2, uint32_t& r3, uint32_t addr) {
    asm volatile("ldmatrix.sync.aligned.m8n8.x4.shared.b16 {%0,%1,%2,%3}, [%4];"
                 : "=r"(r0), "=r"(r1), "=r"(r2), "=r"(r3) : "r"(addr));
}

__device__ __forceinline__ void ldmx4t(uint32_t& r0, uint32_t& r1,
                                       uint32_t& r2, uint32_t& r3, uint32_t addr) {
    asm volatile("ldmatrix.sync.aligned.m8n8.x4.trans.shared.b16 {%0,%1,%2,%3}, [%4];"
                 : "=r"(r0), "=r"(r1), "=r"(r2), "=r"(r3) : "r"(addr));
}

__device__ __forceinline__ void mma16816(float* d, const uint32_t* a,
                                         uint32_t b0, uint32_t b1) {
    asm volatile(
        "mma.sync.aligned.m16n8k16.row.col.f32.bf16.bf16.f32 "
        "{%0,%1,%2,%3}, {%4,%5,%6,%7}, {%8,%9}, {%0,%1,%2,%3};"
        : "+f"(d[0]), "+f"(d[1]), "+f"(d[2]), "+f"(d[3])
        : "r"(a[0]), "r"(a[1]), "r"(a[2]), "r"(a[3]), "r"(b0), "r"(b1));
}

__device__ __forceinline__ uint32_t packbf(float lo, float hi) {
    uint32_t r;
    asm("cvt.rn.bf16x2.f32 %0, %1, %2;" : "=r"(r) : "f"(hi), "f"(lo));
    return r;
}

__device__ __forceinline__ void cp16(uint32_t dst, const void* src) {
    asm volatile("cp.async.cg.shared.global [%0], [%1], 16;" :: "r"(dst), "l"(src));
}
#define CP_COMMIT() asm volatile("cp.async.commit_group;" ::: "memory")
#define CP_WAIT0()  asm volatile("cp.async.wait_group 0;" ::: "memory")
#define CP_WAIT1()  asm volatile("cp.async.wait_group 1;" ::: "memory")

// ---------------------------------------------------------------------------
// bf16x3 GEMM via mma.sync, cp.async 2-stage pipelined.
// 4 warps/CTA (2m x 2n), warp tile 64x64, CTA tile 128x128, BK=32.
// ---------------------------------------------------------------------------
#define SPAD 40
#define GMAT (128 * SPAD * 2u)   // bytes per matrix per stage (10240)

__global__ __launch_bounds__(128, 2)
void gemm_bf16x3(const __nv_bfloat16* __restrict__ Ah,
                 const __nv_bfloat16* __restrict__ Al,
                 const __nv_bfloat16* __restrict__ Bh,
                 const __nv_bfloat16* __restrict__ Bl,
                 const float* __restrict__ bias,
                 float* __restrict__ Cout, int N, int K)
{
    extern __shared__ char gsm[];
    const uint32_t sb = smem_u32(gsm);

    const int tid  = threadIdx.x;
    const int wid  = tid >> 5;
    const int lane = tid & 31;
    const int mw   = wid >> 1;      // 0..1
    const int nw   = wid & 1;       // 0..1
    const int m0   = blockIdx.y * 128;
    const int n0   = blockIdx.x * 128;

    auto stoff = [&](int s, int m) -> uint32_t {
        return sb + (uint32_t)(s * 4 + m) * GMAT;
    };

    // loader: each matrix = 128 rows x 4 x 16B chunks = 512; 4 per thread
    const int kq = K >> 3;
    const int nk = K >> 5;

    auto load_stage = [&](int s, int kc) {
#pragma unroll
        for (int i = 0; i < 4; i++) {
            const int idx = tid + i * 128;
            const int r = idx >> 2, c = idx & 3;
            const uint32_t so = (uint32_t)(r * (SPAD * 2) + c * 16);
            const size_t ga = (size_t)(m0 + r) * kq + kc * 4 + c;
            const size_t gb = (size_t)(n0 + r) * kq + kc * 4 + c;
            cp16(stoff(s, 0) + so, (const uint4*)Ah + ga);
            cp16(stoff(s, 1) + so, (const uint4*)Al + ga);
            cp16(stoff(s, 2) + so, (const uint4*)Bh + gb);
            cp16(stoff(s, 3) + so, (const uint4*)Bl + gb);
        }
    };

    const int lrow = lane & 15;
    const int lk   = (lane >> 4) * 8;
    uint32_t aoff[4], boff[4];
#pragma unroll
    for (int mt = 0; mt < 4; mt++)
        aoff[mt] = (uint32_t)(((mw * 64 + mt * 16 + lrow) * SPAD + lk) * 2);
#pragma unroll
    for (int ng = 0; ng < 4; ng++)
        boff[ng] = (uint32_t)(((nw * 64 + ng * 16 + lrow) * SPAD + lk) * 2);

    float acc[4][8][4];
#pragma unroll
    for (int i = 0; i < 4; i++)
#pragma unroll
        for (int j = 0; j < 8; j++)
#pragma unroll
            for (int e = 0; e < 4; e++) acc[i][j][e] = 0.f;

    load_stage(0, 0);
    CP_COMMIT();

    for (int kc = 0; kc < nk; kc++) {
        const int s = kc & 1;
        if (kc + 1 < nk) {
            load_stage(s ^ 1, kc + 1);
            CP_COMMIT();
            CP_WAIT1();
        } else {
            CP_WAIT0();
        }
        __syncthreads();

        const uint32_t uAh = stoff(s, 0), uAl = stoff(s, 1);
        const uint32_t uBh = stoff(s, 2), uBl = stoff(s, 3);
#pragma unroll
        for (int ks = 0; ks < 2; ks++) {
            const uint32_t kb = ks * 32;
            uint32_t ah[4][4], al[4][4];
#pragma unroll
            for (int mt = 0; mt < 4; mt++) {
                ldmx4(ah[mt][0], ah[mt][1], ah[mt][2], ah[mt][3], uAh + aoff[mt] + kb);
                ldmx4(al[mt][0], al[mt][1], al[mt][2], al[mt][3], uAl + aoff[mt] + kb);
            }
            uint32_t bh[4][4], bl[4][4];
#pragma unroll
            for (int ng = 0; ng < 4; ng++) {
                ldmx4(bh[ng][0], bh[ng][1], bh[ng][2], bh[ng][3], uBh + boff[ng] + kb);
                ldmx4(bl[ng][0], bl[ng][1], bl[ng][2], bl[ng][3], uBl + boff[ng] + kb);
            }
#pragma unroll
            for (int mt = 0; mt < 4; mt++) {
#pragma unroll
                for (int ng = 0; ng < 4; ng++) {
#pragma unroll
                    for (int sub = 0; sub < 2; sub++) {
                        const int nt = ng * 2 + sub;
                        const uint32_t b0 = bh[ng][sub], b1 = bh[ng][sub + 2];
                        const uint32_t c0 = bl[ng][sub], c1 = bl[ng][sub + 2];
                        mma16816(acc[mt][nt], ah[mt], b0, b1);
                        mma16816(acc[mt][nt], ah[mt], c0, c1);
                        mma16816(acc[mt][nt], al[mt], b0, b1);
                    }
                }
            }
        }
        __syncthreads();
    }

    const int erow = lane >> 2;
    const int ecol = (lane & 3) * 2;
#pragma unroll
    for (int mt = 0; mt < 4; mt++) {
#pragma unroll
        for (int nt = 0; nt < 8; nt++) {
            const int row = m0 + mw * 64 + mt * 16 + erow;
            const int col = n0 + nw * 64 + nt * 8 + ecol;
            const float b0 = bias[col], b1 = bias[col + 1];
            float2 v;
            v.x = acc[mt][nt][0] + b0;
            v.y = acc[mt][nt][1] + b1;
            *(float2*)(Cout + (size_t)row * N + col) = v;
            v.x = acc[mt][nt][2] + b0;
            v.y = acc[mt][nt][3] + b1;
            *(float2*)(Cout + (size_t)(row + 8) * N + col) = v;
        }
    }
}
#define GEMM_SMEM (2u * 4u * GMAT)   // 81920

// ---------------------------------------------------------------------------
// fp32 -> (hi,lo) bf16 split, vectorized by 4
// ---------------------------------------------------------------------------
__global__ void split_fp32_bf16(const float4* __restrict__ src,
                                __nv_bfloat162* __restrict__ hi,
                                __nv_bfloat162* __restrict__ lo, int n4)
{
    int i = blockIdx.x * 256 + threadIdx.x;
    if (i >= n4) return;
    float4 v = src[i];
    __nv_bfloat16 hx = __float2bfloat16(v.x);
    __nv_bfloat16 hy = __float2bfloat16(v.y);
    __nv_bfloat16 hz = __float2bfloat16(v.z);
    __nv_bfloat16 hw = __float2bfloat16(v.w);
    __nv_bfloat16 lx = __float2bfloat16(v.x - __bfloat162float(hx));
    __nv_bfloat16 ly = __float2bfloat16(v.y - __bfloat162float(hy));
    __nv_bfloat16 lz = __float2bfloat16(v.z - __bfloat162float(hz));
    __nv_bfloat16 lw = __float2bfloat16(v.w - __bfloat162float(hw));
    __nv_bfloat162 a;
    a.x = hx; a.y = hy; hi[2 * i] = a;
    a.x = hz; a.y = hw; hi[2 * i + 1] = a;
    a.x = lx; a.y = ly; lo[2 * i] = a;
    a.x = lz; a.y = lw; lo[2 * i + 1] = a;
}

// ---------------------------------------------------------------------------
// Fused RoPE + head-major relayout + hi/lo bf16 split of q,k,v.
// ---------------------------------------------------------------------------
__device__ __forceinline__ void split_store4(__nv_bfloat16* ph, __nv_bfloat16* pl,
                                             float a, float b, float c, float d)
{
    __nv_bfloat16 h0 = __float2bfloat16(a), h1 = __float2bfloat16(b);
    __nv_bfloat16 h2 = __float2bfloat16(c), h3 = __float2bfloat16(d);
    __nv_bfloat162 v;
    v.x = h0; v.y = h1; *(__nv_bfloat162*)ph = v;
    v.x = h2; v.y = h3; *(__nv_bfloat162*)(ph + 2) = v;
    v.x = __float2bfloat16(a - __bfloat162float(h0));
    v.y = __float2bfloat16(b - __bfloat162float(h1));
    *(__nv_bfloat162*)pl = v;
    v.x = __float2bfloat16(c - __bfloat162float(h2));
    v.y = __float2bfloat16(d - __bfloat162float(h3));
    *(__nv_bfloat162*)(pl + 2) = v;
}

__global__ void rope_split(const float* __restrict__ cosp,
                           const float* __restrict__ sinp)
{
    int idx = blockIdx.x * 256 + threadIdx.x;
    int ds = idx & 7;
    int h  = (idx >> 3) & 15;
    int t  = (idx >> 7) & 2047;
    int b  = idx >> 18;
    int d0 = ds * 4;

    const float* base = g_qkv + ((size_t)(b * Tt + t)) * (3 * Cc) + h * Dd;
    float4 q1 = *(const float4*)(base + d0);
    float4 q2 = *(const float4*)(base + d0 + 32);
    float4 k1 = *(const float4*)(base + Cc + d0);
    float4 k2 = *(const float4*)(base + Cc + d0 + 32);
    float4 v1 = *(const float4*)(base + 2 * Cc + d0);
    float4 v2 = *(const float4*)(base + 2 * Cc + d0 + 32);
    float4 cw = *(const float4*)(cosp + t * Dd + d0);
    float4 sw = *(const float4*)(sinp + t * Dd + d0);

    const float sc = 0.125f;
    float qa0 = (q1.x * cw.x - q2.x * sw.x) * sc;
    float qa1 = (q1.y * cw.y - q2.y * sw.y) * sc;
    float qa2 = (q1.z * cw.z - q2.z * sw.z) * sc;
    float qa3 = (q1.w * cw.w - q2.w * sw.w) * sc;
    float qb0 = (q2.x * cw.x + q1.x * sw.x) * sc;
    float qb1 = (q2.y * cw.y + q1.y * sw.y) * sc;
    float qb2 = (q2.z * cw.z + q1.z * sw.z) * sc;
    float qb3 = (q2.w * cw.w + q1.w * sw.w) * sc;
    float ka0 = k1.x * cw.x - k2.x * sw.x;
    float ka1 = k1.y * cw.y - k2.y * sw.y;
    float ka2 = k1.z * cw.z - k2.z * sw.z;
    float ka3 = k1.w * cw.w - k2.w * sw.w;
    float kb0 = k2.x * cw.x + k1.x * sw.x;
    float kb1 = k2.y * cw.y + k1.y * sw.y;
    float kb2 = k2.z * cw.z + k1.z * sw.z;
    float kb3 = k2.w * cw.w + k1.w * sw.w;

    size_t ob = (((size_t)(b * NHh + h)) * Tt + t) * Dd;
    split_store4(g_qh + ob + d0,      g_ql + ob + d0,      qa0, qa1, qa2, qa3);
    split_store4(g_qh + ob + d0 + 32, g_ql + ob + d0 + 32, qb0, qb1, qb2, qb3);
    split_store4(g_kh + ob + d0,      g_kl + ob + d0,      ka0, ka1, ka2, ka3);
    split_store4(g_kh + ob + d0 + 32, g_kl + ob + d0 + 32, kb0, kb1, kb2, kb3);
    split_store4(g_vh + ob + d0,      g_vl + ob + d0,      v1.x, v1.y, v1.z, v1.w);
    split_store4(g_vh + ob + d0 + 32, g_vl + ob + d0 + 32, v2.x, v2.y, v2.z, v2.w);
}

// ---------------------------------------------------------------------------
// Flash attention on mma.sync (bf16 hi/lo split, fp32 softmax).
// ---------------------------------------------------------------------------
#define SROW 72
#define TILE_B 9216u

__global__ __launch_bounds__(128, 1) void flash_mma()
{
    extern __shared__ char fsm[];
    const uint32_t sb = smem_u32(fsm);

    const int bh = blockIdx.y;
    const int qt = (gridDim.x - 1) - blockIdx.x;
    const int q0 = qt * 64;
    const int tid = threadIdx.x, wid = tid >> 5, lane = tid & 31;

    const size_t hb = (size_t)bh * Tt * Dd;
    const __nv_bfloat16* Qh = g_qh + hb + (size_t)q0 * Dd;
    const __nv_bfloat16* Ql = g_ql + hb + (size_t)q0 * Dd;
    const __nv_bfloat16* Kh = g_kh + hb;
    const __nv_bfloat16* Kl = g_kl + hb;
    const __nv_bfloat16* Vh = g_vh + hb;
    const __nv_bfloat16* Vl = g_vl + hb;

    auto soff = [&](int buf, int mat) -> uint32_t {
        return sb + (uint32_t)(buf * 4 + mat) * TILE_B;
    };

    {
#pragma unroll
        for (int i = 0; i < 4; i++) {
            int lin = tid + i * 128;
            int r = lin >> 3, c = (lin & 7) * 8;
            uint32_t so = (uint32_t)(r * SROW + c) * 2;
            cp16(soff(1, 0) + so, Qh + (size_t)r * Dd + c);
            cp16(soff(1, 1) + so, Ql + (size_t)r * Dd + c);
        }
        CP_COMMIT();
#pragma unroll
        for (int i = 0; i < 4; i++) {
            int lin = tid + i * 128;
            int r = lin >> 3, c = (lin & 7) * 8;
            uint32_t so = (uint32_t)(r * SROW + c) * 2;
            cp16(soff(0, 0) + so, Kh + (size_t)r * Dd + c);
            cp16(soff(0, 1) + so, Kl + (size_t)r * Dd + c);
            cp16(soff(0, 2) + so, Vh + (size_t)r * Dd + c);
            cp16(soff(0, 3) + so, Vl + (size_t)r * Dd + c);
        }
        CP_COMMIT();
        CP_WAIT0();
        __syncthreads();
    }

    uint32_t QHf[4][4], QLf[4][4];
    {
        const int row = wid * 16 + (lane & 15);
        const int ck  = (lane >> 4) * 8;
#pragma unroll
        for (int kk = 0; kk < 4; kk++) {
            uint32_t ao = (uint32_t)(row * SROW + kk * 16 + ck) * 2;
            ldmx4(QHf[kk][0], QHf[kk][1], QHf[kk][2], QHf[kk][3], soff(1, 0) + ao);
            ldmx4(QLf[kk][0], QLf[kk][1], QLf[kk][2], QLf[kk][3], soff(1, 1) + ao);
        }
    }

    float O[8][4];
#pragma unroll
    for (int i = 0; i < 8; i++)
#pragma unroll
        for (int e = 0; e < 4; e++) O[i][e] = 0.f;
    float m0 = -1e30f, m1 = -1e30f, l0 = 0.f, l1 = 0.f;

    const int klrow = lane & 15;
    const int klk   = (lane >> 4) * 8;
    const int vg    = lane >> 3;
    const int vrow_in = (vg & 1) * 8 + (lane & 7);
    const int vcol_of = (vg >> 1) * 8;

    for (int jt = 0; jt <= qt; jt++) {
        const int buf = jt & 1;
        __syncthreads();
        if (jt < qt) {
            const int j1 = (jt + 1) * 64;
#pragma unroll
            for (int i = 0; i < 4; i++) {
                int lin = tid + i * 128;
                int r = lin >> 3, c = (lin & 7) * 8;
                uint32_t so = (uint32_t)(r * SROW + c) * 2;
                size_t gi = (size_t)(j1 + r) * Dd + c;
                cp16(soff(buf ^ 1, 0) + so, Kh + gi);
                cp16(soff(buf ^ 1, 1) + so, Kl + gi);
                cp16(soff(buf ^ 1, 2) + so, Vh + gi);
                cp16(soff(buf ^ 1, 3) + so, Vl + gi);
            }
            CP_COMMIT();
            CP_WAIT1();
        } else {
            CP_WAIT0();
        }
        __syncthreads();

        float S[8][4];
#pragma unroll
        for (int i = 0; i < 8; i++)
#pragma unroll
            for (int e = 0; e < 4; e++) S[i][e] = 0.f;

#pragma unroll
        for (int jg = 0; jg < 4; jg++) {
#pragma unroll
            for (int kk = 0; kk < 4; kk++) {
                uint32_t ao = (uint32_t)((jg * 16 + klrow) * SROW + kk * 16 + klk) * 2;
                uint32_t kh0, kh1, kh2, kh3, kl0, kl1, kl2, kl3;
                ldmx4(kh0, kh1, kh2, kh3, soff(buf, 0) + ao);
                ldmx4(kl0, kl1, kl2, kl3, soff(buf, 1) + ao);
                mma16816(S[jg * 2 + 0], QHf[kk], kh0, kh2);
                mma16816(S[jg * 2 + 0], QLf[kk], kh0, kh2);
                mma16816(S[jg * 2 + 0], QHf[kk], kl0, kl2);
                mma16816(S[jg * 2 + 1], QHf[kk], kh1, kh3);
                mma16816(S[jg * 2 + 1], QLf[kk], kh1, kh3);
                mma16816(S[jg * 2 + 1], QHf[kk], kl1, kl3);
            }
        }

        if (jt == qt) {
            const int r0l = wid * 16 + (lane >> 2);
            const int cb  = (lane & 3) * 2;
#pragma unroll
            for (int nf = 0; nf < 8; nf++) {
                int c0 = nf * 8 + cb;
                if (c0     > r0l)     S[nf][0] = -1e30f;
                if (c0 + 1 > r0l)     S[nf][1] = -1e30f;
                if (c0     > r0l + 8) S[nf][2] = -1e30f;
                if (c0 + 1 > r0l + 8) S[nf][3] = -1e30f;
            }
        }

        float tm0 = -1e30f, tm1 = -1e30f;
#pragma unroll
        for (int nf = 0; nf < 8; nf++) {
            tm0 = fmaxf(tm0, fmaxf(S[nf][0], S[nf][1]));
            tm1 = fmaxf(tm1, fmaxf(S[nf][2], S[nf][3]));
        }
        tm0 = fmaxf(tm0, __shfl_xor_sync(0xffffffff, tm0, 1));
        tm0 = fmaxf(tm0, __shfl_xor_sync(0xffffffff, tm0, 2));
        tm1 = fmaxf(tm1, __shfl_xor_sync(0xffffffff, tm1, 1));
        tm1 = fmaxf(tm1, __shfl_xor_sync(0xffffffff, tm1, 2));

        float m0n = fmaxf(m0, tm0), m1n = fmaxf(m1, tm1);
        float sc0 = __expf(m0 - m0n), sc1 = __expf(m1 - m1n);
        l0 *= sc0; l1 *= sc1;
#pragma unroll
        for (int i = 0; i < 8; i++) {
            O[i][0] *= sc0; O[i][1] *= sc0;
            O[i][2] *= sc1; O[i][3] *= sc1;
        }
#pragma unroll
        for (int nf = 0; nf < 8; nf++) {
            S[nf][0] = __expf(S[nf][0] - m0n);
            S[nf][1] = __expf(S[nf][1] - m0n);
            S[nf][2] = __expf(S[nf][2] - m1n);
            S[nf][3] = __expf(S[nf][3] - m1n);
            l0 += S[nf][0] + S[nf][1];
            l1 += S[nf][2] + S[nf][3];
        }
        m0 = m0n; m1 = m1n;

#pragma unroll
        for (int kk = 0; kk < 4; kk++) {
            const float* s0 = S[2 * kk];
            const float* s1 = S[2 * kk + 1];
            uint32_t PH[4], PL[4];
            PH[0] = packbf(s0[0], s0[1]);
            PH[1] = packbf(s0[2], s0[3]);
            PH[2] = packbf(s1[0], s1[1]);
            PH[3] = packbf(s1[2], s1[3]);
#pragma unroll
            for (int e = 0; e < 4; e++) {
                const float* sv = (e < 2) ? s0 : s1;
                float c0 = sv[(e & 1) * 2], c1 = sv[(e & 1) * 2 + 1];
                float f0 = __uint_as_float(PH[e] << 16);
                float f1 = __uint_as_float(PH[e] & 0xffff0000u);
                PL[e] = packbf(c0 - f0, c1 - f1);
            }
#pragma unroll
            for (int dc = 0; dc < 4; dc++) {
                uint32_t vo = (uint32_t)((kk * 16 + vrow_in) * SROW + dc * 16 + vcol_of) * 2;
                uint32_t vh0, vh1, vh2, vh3, vl0, vl1, vl2, vl3;
                ldmx4t(vh0, vh1, vh2, vh3, soff(buf, 2) + vo);
                ldmx4t(vl0, vl1, vl2, vl3, soff(buf, 3) + vo);
                mma16816(O[dc * 2 + 0], PH, vh0, vh1);
                mma16816(O[dc * 2 + 0], PL, vh0, vh1);
                mma16816(O[dc * 2 + 0], PH, vl0, vl1);
                mma16816(O[dc * 2 + 1], PH, vh2, vh3);
                mma16816(O[dc * 2 + 1], PL, vh2, vh3);
                mma16816(O[dc * 2 + 1], PH, vl2, vl3);
            }
        }
    }

    l0 += __shfl_xor_sync(0xffffffff, l0, 1);
    l0 += __shfl_xor_sync(0xffffffff, l0, 2);
    l1 += __shfl_xor_sync(0xffffffff, l1, 1);
    l1 += __shfl_xor_sync(0xffffffff, l1, 2);
    const float i0 = 1.f / l0, i1 = 1.f / l1;

    const int b = bh >> 4, h = bh & 15;
    const int t0 = q0 + wid * 16 + (lane >> 2);
    const int t1 = t0 + 8;
    const size_t co = (size_t)h * Dd + (lane & 3) * 2;
    __nv_bfloat16* ah0 = g_ah + ((size_t)(b * Tt + t0)) * Cc + co;
    __nv_bfloat16* al0 = g_al + ((size_t)(b * Tt + t0)) * Cc + co;
    __nv_bfloat16* ah1 = g_ah + ((size_t)(b * Tt + t1)) * Cc + co;
    __nv_bfloat16* al1 = g_al + ((size_t)(b * Tt + t1)) * Cc + co;
#pragma unroll
    for (int nf = 0; nf < 8; nf++) {
        float v0 = O[nf][0] * i0, v1 = O[nf][1] * i0;
        float v2 = O[nf][2] * i1, v3 = O[nf][3] * i1;
        __nv_bfloat16 h0 = __float2bfloat16(v0), h1 = __float2bfloat16(v1);
        __nv_bfloat16 h2 = __float2bfloat16(v2), h3 = __float2bfloat16(v3);
        __nv_bfloat162 w;
        w.x = h0; w.y = h1; *(__nv_bfloat162*)(ah0 + nf * 8) = w;
        w.x = h2; w.y = h3; *(__nv_bfloat162*)(ah1 + nf * 8) = w;
        w.x = __float2bfloat16(v0 - __bfloat162float(h0));
        w.y = __float2bfloat16(v1 - __bfloat162float(h1));
        *(__nv_bfloat162*)(al0 + nf * 8) = w;
        w.x = __float2bfloat16(v2 - __bfloat162float(h2));
        w.y = __float2bfloat16(v3 - __bfloat162float(h3));
        *(__nv_bfloat162*)(al1 + nf * 8) = w;
    }
}

// ---------------------------------------------------------------------------
extern "C" void kernel_launch(void* const* d_in, const int* in_sizes, int n_in,
                              void* d_out, int out_size)
{
    const float* x      = (const float*)d_in[0];
    const float* w_attn = (const float*)d_in[1];
    const float* b_attn = (const float*)d_in[2];
    const float* w_proj = (const float*)d_in[3];
    const float* b_proj = (const float*)d_in[4];
    const float* cosp   = (const float*)d_in[5];
    const float* sinp   = (const float*)d_in[6];
    float* out = (float*)d_out;

    void *p_xh, *p_xl, *p_wh, *p_wl, *p_ph, *p_pl, *p_ah, *p_al, *p_qkv;
    cudaGetSymbolAddress(&p_xh, g_xh);
    cudaGetSymbolAddress(&p_xl, g_xl);
    cudaGetSymbolAddress(&p_wh, g_wh);
    cudaGetSymbolAddress(&p_wl, g_wl);
    cudaGetSymbolAddress(&p_ph, g_ph);
    cudaGetSymbolAddress(&p_pl, g_pl);
    cudaGetSymbolAddress(&p_ah, g_ah);
    cudaGetSymbolAddress(&p_al, g_al);
    cudaGetSymbolAddress(&p_qkv, g_qkv);

    static bool once = false;
    if (!once) {
        cudaFuncSetAttribute(flash_mma,
                             cudaFuncAttributeMaxDynamicSharedMemorySize, 8 * TILE_B);
        cudaFuncSetAttribute(gemm_bf16x3,
                             cudaFuncAttributeMaxDynamicSharedMemorySize, GEMM_SMEM);
        cudaFuncSetAttribute(gemm_bf16x3,
                             cudaFuncAttributePreferredSharedMemoryCarveout, 100);
        once = true;
    }

    // 1) splits of x, w_attn, w_proj
    {
        int n4 = (Mtot * Cc) / 4;
        split_fp32_bf16<<<(n4 + 255) / 256, 256>>>(
            (const float4*)x, (__nv_bfloat162*)p_xh, (__nv_bfloat162*)p_xl, n4);
    }
    {
        int n4 = (3 * Cc * Cc) / 4;
        split_fp32_bf16<<<(n4 + 255) / 256, 256>>>(
            (const float4*)w_attn, (__nv_bfloat162*)p_wh, (__nv_bfloat162*)p_wl, n4);
    }
    {
        int n4 = (Cc * Cc) / 4;
        split_fp32_bf16<<<(n4 + 255) / 256, 256>>>(
            (const float4*)w_proj, (__nv_bfloat162*)p_ph, (__nv_bfloat162*)p_pl, n4);
    }

    // 2) QKV projection (pipelined tensor-core GEMM) -> g_qkv fp32
    {
        dim3 grid((3 * Cc) / 128, Mtot / 128);
        gemm_bf16x3<<<grid, 128, GEMM_SMEM>>>(
            (const __nv_bfloat16*)p_xh, (const __nv_bfloat16*)p_xl,
            (const __nv_bfloat16*)p_wh, (const __nv_bfloat16*)p_wl,
            b_attn, (float*)p_qkv, 3 * Cc, Cc);
    }

    // 3) fused RoPE + relayout + bf16 split of q,k,v
    {
        int total = Bb * Tt * NHh * 8;
        rope_split<<<total / 256, 256>>>(cosp, sinp);
    }

    // 4) flash attention -> g_ah/g_al bf16 (direct)
    {
        dim3 grid(Tt / 64, Bb * NHh);
        flash_mma<<<grid, 128, 8 * TILE_B>>>();
    }

    // 5) output projection
    {
        dim3 grid(Cc / 128, Mtot / 128);
        gemm_bf16x3<<<grid, 128, GEMM_SMEM>>>(
            (const __nv_bfloat16*)p_ah, (const __nv_bfloat16*)p_al,
            (const __nv_bfloat16*)p_ph, (const __nv_bfloat16*)p_pl,
            b_proj, out, Cc, Cc);
    }
}